// round 11
// baseline (speedup 1.0000x reference)
#include <cuda_runtime.h>

// Equivariant linear: RS = [(16,0),(16,1),(16,2)], dim = 144, BATCH = 262144.
// Block-diagonal per (l,m): out[z,l,v,t] = sum_u Wl[v,u] * x[z,l,u,t],
// Wl[v,u] = weight[l*256 + v*16 + u] * 0.25 / sqrt(2l+1).
// Row layout: l=0 cols [0,16) d=1; l=1 idx 16+u*3+t; l=2 idx 64+u*5+t.
//
// R11: 192-thread CTAs (6 warps) on 32-row tiles -> 10 CTAs/SM = 60 warps
// (latency hiding via occupancy). W in __constant__ (LDC port), f32x2 FMAs,
// conflict-free stride-145 smem.

#define ROWS 32
#define STRIDE 145      // odd -> row-axis scalar gather/scatter conflict-free
#define NT 192          // 6 warps
#define DIM 144
#define EPT 24          // 32*144 / 192 staged elements per thread

typedef unsigned long long ull;

__constant__ __align__(16) float cW[768];   // raw weights, W[l][v][u]

__device__ __forceinline__ ull pack_dup(float x) {
    ull r;
    asm("mov.b64 %0, {%1, %1};" : "=l"(r) : "f"(x));
    return r;
}
__device__ __forceinline__ ull pack2(float lo, float hi) {
    ull r;
    asm("mov.b64 %0, {%1, %2};" : "=l"(r) : "f"(lo), "f"(hi));
    return r;
}
__device__ __forceinline__ ull mul2(ull a, ull b) {
    ull r;
    asm("mul.rn.f32x2 %0, %1, %2;" : "=l"(r) : "l"(a), "l"(b));
    return r;
}
__device__ __forceinline__ void ffma2(ull& acc, ull w2, ull x2) {
    asm("fma.rn.f32x2 %0, %1, %2, %0;" : "+l"(acc) : "l"(w2), "l"(x2));
}
__device__ __forceinline__ float hadd2(ull p) {
    float lo, hi;
    asm("mov.b64 {%0, %1}, %2;" : "=f"(lo), "=f"(hi) : "l"(p));
    return lo + hi;
}

__device__ __forceinline__ void do_slice(int s, float* sD, int lane) {
    int l, off, d;
    float scale;
    if (s == 0)      { l = 0; off = 0;            d = 1; scale = 0.25f; }
    else if (s < 4)  { l = 1; off = 16 + (s - 1); d = 3;
                       scale = 0.25f * 0.57735026918962576f; }  // 1/sqrt(3)
    else             { l = 2; off = 64 + (s - 4); d = 5;
                       scale = 0.25f * 0.44721359549995794f; }  // 1/sqrt(5)

    float* p = sD + lane * STRIDE + off;
    const ull sc2 = pack_dup(scale);

    // Gather + pack + scale the 16 inputs (u-paired f32x2).
    ull xr[8];
    #pragma unroll
    for (int up = 0; up < 8; up++)
        xr[up] = mul2(pack2(p[(2*up) * d], p[(2*up+1) * d]), sc2);

    // v-outer matvec; W row W[l][v][0..15] contiguous -> warp-uniform
    // LDC.128 x4 on the constant port (off the L1/smem pipe).
    const ulonglong2* __restrict__ w2 =
        reinterpret_cast<const ulonglong2*>(cW + l * 256);
    #pragma unroll
    for (int v = 0; v < 16; v++) {
        ulonglong2 wa = w2[v * 4 + 0];
        ulonglong2 wb = w2[v * 4 + 1];
        ulonglong2 wc = w2[v * 4 + 2];
        ulonglong2 wd = w2[v * 4 + 3];

        ull a = 0ull;
        ffma2(a, wa.x, xr[0]);
        ffma2(a, wa.y, xr[1]);
        ffma2(a, wb.x, xr[2]);
        ffma2(a, wb.y, xr[3]);
        ffma2(a, wc.x, xr[4]);
        ffma2(a, wc.y, xr[5]);
        ffma2(a, wd.x, xr[6]);
        ffma2(a, wd.y, xr[7]);

        p[v * d] = hadd2(a);       // conflict-free scalar STS
    }
}

__global__ __launch_bounds__(NT) void eq_linear_kernel(
    const float* __restrict__ x,
    float* __restrict__ y)
{
    __shared__ float sD[ROWS * STRIDE];

    const int tid  = threadIdx.x;
    const int lane = tid & 31;
    const int wrp  = tid >> 5;      // 0..5

    const long long row0 = (long long)blockIdx.x * ROWS;

    // Coalesced scalar tile load. i = tid + 192k; incremental (r,c):
    // +192 elements = +1 row +48 cols (carry a second row when c wraps).
    // Consecutive lanes -> consecutive addresses (LDG 1 wf, STS ~conflict-free).
    {
        const float* __restrict__ gsrc = x + row0 * DIM + tid;
        int saddr = (tid / DIM) * STRIDE + (tid % DIM);
        int c     = tid % DIM;
        #pragma unroll
        for (int k = 0; k < EPT; k++) {
            sD[saddr] = gsrc[k * NT];
            saddr += STRIDE + 48;           // +1 row, +48 cols
            c += 48;
            if (c >= DIM) { c -= DIM; saddr += 1; }   // extra-row carry (+145-144)
        }
    }
    __syncthreads();

    // Compute: 9 slices over 6 warps (warps 0-2 take a second slice).
    do_slice(wrp, sD, lane);
    if (wrp < 3) do_slice(wrp + 6, sD, lane);
    __syncthreads();

    // Coalesced scalar store (mirror of the load).
    {
        float* __restrict__ gdst = y + row0 * DIM + tid;
        int saddr = (tid / DIM) * STRIDE + (tid % DIM);
        int c     = tid % DIM;
        #pragma unroll
        for (int k = 0; k < EPT; k++) {
            gdst[k * NT] = sD[saddr];
            saddr += STRIDE + 48;
            c += 48;
            if (c >= DIM) { c -= DIM; saddr += 1; }
        }
    }
}

extern "C" void kernel_launch(void* const* d_in, const int* in_sizes, int n_in,
                              void* d_out, int out_size)
{
    const float* feat = (const float*)d_in[0];
    const float* w    = (const float*)d_in[1];
    float* out        = (float*)d_out;

    // Raw weights -> constant bank (D2D async memcpy node; graph-capturable).
    cudaMemcpyToSymbolAsync(cW, w, 768 * sizeof(float), 0,
                            cudaMemcpyDeviceToDevice, 0);

    const int batch  = in_sizes[0] / DIM;   // 262144
    const int blocks = batch / ROWS;        // 8192

    eq_linear_kernel<<<blocks, NT>>>(feat, out);
}

// round 12
// speedup vs baseline: 1.5534x; 1.5534x over previous
#include <cuda_runtime.h>

// Equivariant linear: RS = [(16,0),(16,1),(16,2)], dim = 144, BATCH = 262144.
// Block-diagonal per (l,m): out[z,l,v,t] = sum_u Wl[v,u] * x[z,l,u,t],
// Wl[v,u] = weight[l*256 + v*16 + u] * 0.25 / sqrt(2l+1).
// Row layout: l=0 cols [0,16) d=1; l=1 idx 16+u*3+t; l=2 idx 64+u*5+t.
//
// R12: 4-plane deinterleaved smem (plane j holds col%4==j at row stride 37,
// odd -> conflict-free scalar gathers) so global I/O is LDG.128/STG.128
// (4x MLP) while ALL smem accesses stay 1-wavefront. W in __constant__
// (LDC port). 128-thread CTAs, 32-row tiles, 1 row/thread compute.

#define ROWS 32
#define PLANE 1184      // 32 * 37 floats per plane
#define NT 128          // 4 warps
#define DIM 144
#define NV4 1152        // 32 * 36 float4 per tile

typedef unsigned long long ull;

__constant__ __align__(16) float cW[768];   // raw weights, W[l][v][u]

__device__ __forceinline__ ull pack_dup(float x) {
    ull r;
    asm("mov.b64 %0, {%1, %1};" : "=l"(r) : "f"(x));
    return r;
}
__device__ __forceinline__ ull pack2(float lo, float hi) {
    ull r;
    asm("mov.b64 %0, {%1, %2};" : "=l"(r) : "f"(lo), "f"(hi));
    return r;
}
__device__ __forceinline__ ull mul2(ull a, ull b) {
    ull r;
    asm("mul.rn.f32x2 %0, %1, %2;" : "=l"(r) : "l"(a), "l"(b));
    return r;
}
__device__ __forceinline__ void ffma2(ull& acc, ull w2, ull x2) {
    asm("fma.rn.f32x2 %0, %1, %2, %0;" : "+l"(acc) : "l"(w2), "l"(x2));
}
__device__ __forceinline__ float hadd2(ull p) {
    float lo, hi;
    asm("mov.b64 {%0, %1}, %2;" : "=f"(lo), "=f"(hi) : "l"(p));
    return lo + hi;
}

__device__ __forceinline__ void do_slice(int s, float* __restrict__ sD, int lane) {
    int l, off, d;
    float scale;
    if (s == 0)      { l = 0; off = 0;            d = 1; scale = 0.25f; }
    else if (s < 4)  { l = 1; off = 16 + (s - 1); d = 3;
                       scale = 0.25f * 0.57735026918962576f; }  // 1/sqrt(3)
    else             { l = 2; off = 64 + (s - 4); d = 5;
                       scale = 0.25f * 0.44721359549995794f; }  // 1/sqrt(5)

    const int base = lane * 37;
    const ull sc2 = pack_dup(scale);

    // Gather 16 inputs from planes (conflict-free: lane stride 37, odd),
    // pack u-pairs, fold in scale.
    ull xr[8];
    {
        int idx = off;
        #pragma unroll
        for (int up = 0; up < 8; up++) {
            float lo = sD[(idx & 3) * PLANE + base + (idx >> 2)];
            idx += d;
            float hi = sD[(idx & 3) * PLANE + base + (idx >> 2)];
            idx += d;
            xr[up] = mul2(pack2(lo, hi), sc2);
        }
    }

    // v-outer matvec; W row contiguous -> warp-uniform LDC.128 x4 on the
    // constant port (off the L1/smem pipe). Scatter results back to planes.
    const ulonglong2* __restrict__ w2 =
        reinterpret_cast<const ulonglong2*>(cW + l * 256);
    int idx = off;
    #pragma unroll
    for (int v = 0; v < 16; v++) {
        ulonglong2 wa = w2[v * 4 + 0];
        ulonglong2 wb = w2[v * 4 + 1];
        ulonglong2 wc = w2[v * 4 + 2];
        ulonglong2 wd = w2[v * 4 + 3];

        ull a = 0ull;
        ffma2(a, wa.x, xr[0]);
        ffma2(a, wa.y, xr[1]);
        ffma2(a, wb.x, xr[2]);
        ffma2(a, wb.y, xr[3]);
        ffma2(a, wc.x, xr[4]);
        ffma2(a, wc.y, xr[5]);
        ffma2(a, wd.x, xr[6]);
        ffma2(a, wd.y, xr[7]);

        sD[(idx & 3) * PLANE + base + (idx >> 2)] = hadd2(a);
        idx += d;
    }
}

__global__ __launch_bounds__(NT) void eq_linear_kernel(
    const float* __restrict__ x,
    float* __restrict__ y)
{
    __shared__ float sD[4 * PLANE];

    const int tid  = threadIdx.x;
    const int lane = tid & 31;
    const int wrp  = tid >> 5;      // 0..3

    const long long row0 = (long long)blockIdx.x * ROWS;

    // Load: LDG.128 (coalesced), deinterleave into 4 planes with scalar STS
    // at lane-consecutive addresses (1 wf each).
    {
        const float4* __restrict__ gsrc =
            reinterpret_cast<const float4*>(x) + row0 * 36;
        #pragma unroll
        for (int k = 0; k < 9; k++) {
            int i  = tid + k * NT;          // 0..1151
            int r  = i / 36;
            int c4 = i % 36;
            float4 v = gsrc[i];
            int a = r * 37 + c4;
            sD[a]             = v.x;
            sD[a + PLANE]     = v.y;
            sD[a + 2 * PLANE] = v.z;
            sD[a + 3 * PLANE] = v.w;
        }
    }
    __syncthreads();

    // Compute: 9 slices over 4 warps; lane = row.
    do_slice(wrp, sD, lane);
    do_slice(wrp + 4, sD, lane);
    if (wrp == 3) do_slice(8, sD, lane);
    __syncthreads();

    // Store: re-interleave from planes (conflict-free LDS), STG.128.
    {
        float4* __restrict__ gdst =
            reinterpret_cast<float4*>(y) + row0 * 36;
        #pragma unroll
        for (int k = 0; k < 9; k++) {
            int i  = tid + k * NT;
            int r  = i / 36;
            int c4 = i % 36;
            int a = r * 37 + c4;
            float4 v;
            v.x = sD[a];
            v.y = sD[a + PLANE];
            v.z = sD[a + 2 * PLANE];
            v.w = sD[a + 3 * PLANE];
            gdst[i] = v;
        }
    }
}

extern "C" void kernel_launch(void* const* d_in, const int* in_sizes, int n_in,
                              void* d_out, int out_size)
{
    const float* feat = (const float*)d_in[0];
    const float* w    = (const float*)d_in[1];
    float* out        = (float*)d_out;

    // Raw weights -> constant bank (D2D async memcpy node; graph-capturable).
    cudaMemcpyToSymbolAsync(cW, w, 768 * sizeof(float), 0,
                            cudaMemcpyDeviceToDevice, 0);

    const int batch  = in_sizes[0] / DIM;   // 262144
    const int blocks = batch / ROWS;        // 8192

    eq_linear_kernel<<<blocks, NT>>>(feat, out);
}

// round 13
// speedup vs baseline: 1.6141x; 1.0390x over previous
#include <cuda_runtime.h>

// Equivariant linear: RS = [(16,0),(16,1),(16,2)], dim = 144, BATCH = 262144.
// Block-diagonal per (l,m): out[z,l,v,t] = sum_u Wl[v,u] * x[z,l,u,t],
// Wl[v,u] = weight[l*256 + v*16 + u] * 0.25 / sqrt(2l+1).
// Row layout: l=0 cols [0,16) d=1; l=1 idx 16+u*3+t; l=2 idx 64+u*5+t.
//
// R13: R12's 4-plane deinterleaved smem (conflict-free everywhere, LDG.128
// global I/O) + fully templated slices (all smem/const addresses fold to
// immediates) + 3 balanced warps (3 slices each) + div-free staging index.

#define ROWS 32
#define PLANE 1184      // 32 * 37 floats per plane
#define NT 96           // 3 warps; warp w -> slices {w, w+3, w+6}
#define DIM 144
#define EPT 12          // 1152 float4 / 96 threads

typedef unsigned long long ull;

__constant__ __align__(16) float cW[768];   // raw weights, W[l][v][u]

__device__ __forceinline__ ull pack_dup(float x) {
    ull r;
    asm("mov.b64 %0, {%1, %1};" : "=l"(r) : "f"(x));
    return r;
}
__device__ __forceinline__ ull pack2(float lo, float hi) {
    ull r;
    asm("mov.b64 %0, {%1, %2};" : "=l"(r) : "f"(lo), "f"(hi));
    return r;
}
__device__ __forceinline__ ull mul2(ull a, ull b) {
    ull r;
    asm("mul.rn.f32x2 %0, %1, %2;" : "=l"(r) : "l"(a), "l"(b));
    return r;
}
__device__ __forceinline__ void ffma2(ull& acc, ull w2, ull x2) {
    asm("fma.rn.f32x2 %0, %1, %2, %0;" : "+l"(acc) : "l"(w2), "l"(x2));
}
__device__ __forceinline__ float hadd2(ull p) {
    float lo, hi;
    asm("mov.b64 {%0, %1}, %2;" : "=f"(lo), "=f"(hi) : "l"(p));
    return lo + hi;
}

// Fully constant-folded slice: S compile-time -> every smem/const address is
// base + immediate; scale folded at compile time.
template<int S>
__device__ __forceinline__ void do_slice(float* __restrict__ sD, int base) {
    constexpr int l   = (S == 0) ? 0 : (S < 4) ? 1 : 2;
    constexpr int off = (S == 0) ? 0 : (S < 4) ? 16 + (S - 1) : 64 + (S - 4);
    constexpr int d   = (l == 0) ? 1 : (l == 1) ? 3 : 5;
    constexpr float scale =
        (l == 0) ? 0.25f
      : (l == 1) ? 0.25f * 0.57735026918962576f    // 1/sqrt(3)
                 : 0.25f * 0.44721359549995794f;   // 1/sqrt(5)

    const ull sc2 = pack_dup(scale);

    // Gather 16 inputs from planes (immediate offsets), pack u-pairs, scale.
    ull xr[8];
    #pragma unroll
    for (int up = 0; up < 8; up++) {
        constexpr int dummy = 0; (void)dummy;
        int i0 = off + (2 * up) * d;       // folds to constant after unroll
        int i1 = i0 + d;
        float lo = sD[(i0 & 3) * PLANE + (i0 >> 2) + base];
        float hi = sD[(i1 & 3) * PLANE + (i1 >> 2) + base];
        xr[up] = mul2(pack2(lo, hi), sc2);
    }

    // v-outer matvec; warp-uniform LDC.128 x4 on the constant port.
    const ulonglong2* __restrict__ w2 =
        reinterpret_cast<const ulonglong2*>(cW + l * 256);
    #pragma unroll
    for (int v = 0; v < 16; v++) {
        ulonglong2 wa = w2[v * 4 + 0];
        ulonglong2 wb = w2[v * 4 + 1];
        ulonglong2 wc = w2[v * 4 + 2];
        ulonglong2 wd = w2[v * 4 + 3];

        ull a = 0ull;
        ffma2(a, wa.x, xr[0]);
        ffma2(a, wa.y, xr[1]);
        ffma2(a, wb.x, xr[2]);
        ffma2(a, wb.y, xr[3]);
        ffma2(a, wc.x, xr[4]);
        ffma2(a, wc.y, xr[5]);
        ffma2(a, wd.x, xr[6]);
        ffma2(a, wd.y, xr[7]);

        int iv = off + v * d;              // folds to constant
        sD[(iv & 3) * PLANE + (iv >> 2) + base] = hadd2(a);
    }
}

__global__ __launch_bounds__(NT) void eq_linear_kernel(
    const float* __restrict__ x,
    float* __restrict__ y)
{
    __shared__ float sD[4 * PLANE];

    const int tid  = threadIdx.x;
    const int lane = tid & 31;
    const int wrp  = tid >> 5;      // 0..2

    const long long row0 = (long long)blockIdx.x * ROWS;

    // Load: LDG.128 coalesced, deinterleave into 4 planes (scalar STS at
    // lane-consecutive addresses -> 1 wf). Plane addr a = i + i/36,
    // maintained incrementally (i += 96 => q += 2, rem += 24, carry).
    {
        const float4* __restrict__ gsrc =
            reinterpret_cast<const float4*>(x) + row0 * 36;
        int q   = tid / 36;
        int rem = tid - q * 36;
        int i   = tid;
        #pragma unroll
        for (int k = 0; k < EPT; k++) {
            float4 v = gsrc[i];
            int a = i + q;                 // == r*37 + c4
            sD[a]             = v.x;
            sD[a + PLANE]     = v.y;
            sD[a + 2 * PLANE] = v.z;
            sD[a + 3 * PLANE] = v.w;
            i += NT; q += 2; rem += 24;
            if (rem >= 36) { rem -= 36; q += 1; }
        }
    }
    __syncthreads();

    // Compute: 3 balanced warps x 3 templated slices; lane = row.
    {
        const int base = lane * 37;
        if (wrp == 0)      { do_slice<0>(sD, base); do_slice<3>(sD, base); do_slice<6>(sD, base); }
        else if (wrp == 1) { do_slice<1>(sD, base); do_slice<4>(sD, base); do_slice<7>(sD, base); }
        else               { do_slice<2>(sD, base); do_slice<5>(sD, base); do_slice<8>(sD, base); }
    }
    __syncthreads();

    // Store: re-interleave from planes (conflict-free LDS), STG.128.
    {
        float4* __restrict__ gdst =
            reinterpret_cast<float4*>(y) + row0 * 36;
        int q   = tid / 36;
        int rem = tid - q * 36;
        int i   = tid;
        #pragma unroll
        for (int k = 0; k < EPT; k++) {
            int a = i + q;
            float4 v;
            v.x = sD[a];
            v.y = sD[a + PLANE];
            v.z = sD[a + 2 * PLANE];
            v.w = sD[a + 3 * PLANE];
            gdst[i] = v;
            i += NT; q += 2; rem += 24;
            if (rem >= 36) { rem -= 36; q += 1; }
        }
    }
}

extern "C" void kernel_launch(void* const* d_in, const int* in_sizes, int n_in,
                              void* d_out, int out_size)
{
    const float* feat = (const float*)d_in[0];
    const float* w    = (const float*)d_in[1];
    float* out        = (float*)d_out;

    // Raw weights -> constant bank (D2D async memcpy node; graph-capturable).
    cudaMemcpyToSymbolAsync(cW, w, 768 * sizeof(float), 0,
                            cudaMemcpyDeviceToDevice, 0);

    const int batch  = in_sizes[0] / DIM;   // 262144
    const int blocks = batch / ROWS;        // 8192

    eq_linear_kernel<<<blocks, NT>>>(feat, out);
}